// round 5
// baseline (speedup 1.0000x reference)
#include <cuda_runtime.h>
#include <cuda_bf16.h>

// Problem constants (GCN_55499567399154)
#define NMAX 50000
#define EMAX 800000
#define FIN  128
#define HID  128
#define NCLS 64

// ---------------- static scratch (no allocations allowed) ----------------
// Device-global symbols are ONLY referenced from device code.
__device__ __align__(256) float d_bufX[NMAX * HID];   // node features (layer input)
__device__ __align__(256) float d_bufG[NMAX * HID];   // g = dinv * (X @ W)
__device__ __align__(256) float d_dinv[NMAX];
__device__ __align__(256) int   d_deg[NMAX];
__device__ __align__(256) int   d_off[NMAX + 8];
__device__ __align__(256) int   d_cur[NMAX];
__device__ __align__(256) int   d_csr[EMAX];
__device__ __align__(256) int   d_bsum[512];
__device__ int d_is64;   // 1 if edge_index is int64, 0 if int32

// ---------------- edge index dtype detection + accessors ----------------
// For int64 (little-endian) all odd 32-bit words are high words == 0
// (node ids < 50000). For int32 they are random source node ids.
__global__ void detect_kernel(const int* __restrict__ p, int E) {
    if (blockIdx.x == 0 && threadIdx.x == 0) {
        int is64 = 1;
        int cnt = (E < 256) ? E : 256;
        for (int i = 0; i < cnt; i++)
            if (p[2 * i + 1] != 0) { is64 = 0; break; }
        d_is64 = is64;
    }
}

__device__ __forceinline__ int edge_src(const int* p, int E, int e) {
    return d_is64 ? p[2 * e] : p[e];
}
__device__ __forceinline__ int edge_dst(const int* p, int E, int e) {
    return d_is64 ? p[2 * (E + e)] : p[E + e];
}

// ---------------- graph build ----------------
__global__ void deg_init_kernel(int n) {
    int i = blockIdx.x * blockDim.x + threadIdx.x;
    if (i < n) d_deg[i] = 1;  // self-loop
}

__global__ void hist_kernel(const int* __restrict__ ei, int E) {
    int e = blockIdx.x * blockDim.x + threadIdx.x;
    if (e < E) atomicAdd(&d_deg[edge_dst(ei, E, e)], 1);
}

// exclusive scan of (deg-1) -> d_off (CSR holds real edges only)
__global__ void scan1_kernel(int n) {
    __shared__ int sh[512];
    int tid = threadIdx.x;
    int i = blockIdx.x * 512 + tid;
    int v = (i < n) ? (d_deg[i] - 1) : 0;
    sh[tid] = v;
    __syncthreads();
#pragma unroll
    for (int dlt = 1; dlt < 512; dlt <<= 1) {
        int t = (tid >= dlt) ? sh[tid - dlt] : 0;
        __syncthreads();
        sh[tid] += t;
        __syncthreads();
    }
    if (i < n) d_off[i] = sh[tid] - v;            // block-local exclusive
    if (tid == 511) d_bsum[blockIdx.x] = sh[511]; // block total
}

__global__ void scan2_kernel(int nb, int n) {
    __shared__ int sh[512];
    int tid = threadIdx.x;
    int v = (tid < nb) ? d_bsum[tid] : 0;
    sh[tid] = v;
    __syncthreads();
#pragma unroll
    for (int dlt = 1; dlt < 512; dlt <<= 1) {
        int t = (tid >= dlt) ? sh[tid - dlt] : 0;
        __syncthreads();
        sh[tid] += t;
        __syncthreads();
    }
    if (tid < nb) d_bsum[tid] = sh[tid] - v;  // exclusive block bases
    if (tid == 0) d_off[n] = sh[511];         // grand total = E
}

__global__ void scan3_kernel(int n) {
    int i = blockIdx.x * blockDim.x + threadIdx.x;
    if (i < n) {
        int o = d_off[i] + d_bsum[i >> 9];
        d_off[i] = o;
        d_cur[i] = o;
        d_dinv[i] = rsqrtf((float)d_deg[i]);
    }
}

__global__ void fill_kernel(const int* __restrict__ ei, int E) {
    int e = blockIdx.x * blockDim.x + threadIdx.x;
    if (e < E) {
        int c = edge_dst(ei, E, e);
        int p = atomicAdd(&d_cur[c], 1);
        d_csr[p] = edge_src(ei, E, e);
    }
}

// ---------------- GEMM: G = dinv .* (X @ W), K=128, OUT = 16*TN ----------------
// block tile: 128 rows x OUT cols, 256 threads, per-thread 8 x TN fp32 FFMA.
// SRC_GLOBAL: read X from internal d_bufX (device symbol) instead of param.
template <int TN, bool SRC_GLOBAL>
__global__ void __launch_bounds__(256) gemm_scale_kernel(
    const float* __restrict__ Xparam, const float* __restrict__ W, int n) {
    constexpr int OUT = 16 * TN;
    constexpr int K = 128;
    constexpr int BK = 32;
    __shared__ float Xs[BK][132];   // transposed: Xs[k][r], pad for banks
    __shared__ float Ws[BK][OUT];   // Ws[k][c]

    const float* X = SRC_GLOBAL ? d_bufX : Xparam;

    const int t = threadIdx.x;
    const int ty = t >> 4;   // 0..15 : rows ty*8..+8
    const int tx = t & 15;   // 0..15 : cols tx*TN..+TN
    const int row0 = blockIdx.x * 128;

    float acc[8][TN];
#pragma unroll
    for (int i = 0; i < 8; i++)
#pragma unroll
        for (int j = 0; j < TN; j++) acc[i][j] = 0.f;

    for (int kb = 0; kb < K; kb += BK) {
        // load X chunk (128 rows x 32 k), transpose into smem
#pragma unroll
        for (int it = 0; it < 4; ++it) {
            int v = t + it * 256;      // 0..1023 float4 slots
            int r = v >> 3;            // 8 float4 per row
            int kq = v & 7;
            float4 val = make_float4(0.f, 0.f, 0.f, 0.f);
            int gr = row0 + r;
            if (gr < n) val = *(const float4*)(X + (size_t)gr * K + kb + kq * 4);
            Xs[kq * 4 + 0][r] = val.x;
            Xs[kq * 4 + 1][r] = val.y;
            Xs[kq * 4 + 2][r] = val.z;
            Xs[kq * 4 + 3][r] = val.w;
        }
        // load W chunk (32 x OUT)
#pragma unroll
        for (int it = 0; it < (BK * OUT / 4) / 256; ++it) {
            int v = t + it * 256;
            int k = v / (OUT / 4);
            int c4 = v % (OUT / 4);
            *(float4*)&Ws[k][c4 * 4] =
                *(const float4*)(W + (size_t)(kb + k) * OUT + c4 * 4);
        }
        __syncthreads();

#pragma unroll
        for (int k = 0; k < BK; ++k) {
            float4 a0 = *(const float4*)&Xs[k][ty * 8];
            float4 a1 = *(const float4*)&Xs[k][ty * 8 + 4];
            float a[8] = {a0.x, a0.y, a0.z, a0.w, a1.x, a1.y, a1.z, a1.w};
            float w[TN];
#pragma unroll
            for (int j = 0; j < TN / 4; j++) {
                float4 wv = *(const float4*)&Ws[k][tx * TN + 4 * j];
                w[4 * j + 0] = wv.x; w[4 * j + 1] = wv.y;
                w[4 * j + 2] = wv.z; w[4 * j + 3] = wv.w;
            }
#pragma unroll
            for (int i = 0; i < 8; i++)
#pragma unroll
                for (int j = 0; j < TN; j++)
                    acc[i][j] = fmaf(a[i], w[j], acc[i][j]);
        }
        __syncthreads();
    }

    // epilogue: scale by dinv[row] and store to d_bufG (stride OUT)
#pragma unroll
    for (int i = 0; i < 8; i++) {
        int gr = row0 + ty * 8 + i;
        if (gr < n) {
            float dv = d_dinv[gr];
            float* dst = d_bufG + (size_t)gr * OUT + tx * TN;
#pragma unroll
            for (int q = 0; q < TN / 4; q++)
                *(float4*)(dst + 4 * q) =
                    make_float4(acc[i][4 * q] * dv, acc[i][4 * q + 1] * dv,
                                acc[i][4 * q + 2] * dv, acc[i][4 * q + 3] * dv);
        }
    }
}

// ---------------- aggregation: Y[c] = relu?(dinv[c]*(sum_in g + g[c]) + b) ----------------
// OUT_PARAM: write to Yparam (harness buffer) instead of internal d_bufX.
template <int F, bool RELU, bool OUT_PARAM>
__global__ void __launch_bounds__(256) agg_kernel(
    const float* __restrict__ bias, float* __restrict__ Yparam, int n) {
    constexpr int V = F / 32;  // floats per lane (4 or 2)
    int gw = (blockIdx.x * 256 + threadIdx.x) >> 5;
    int lane = threadIdx.x & 31;
    if (gw >= n) return;

    float* Y = OUT_PARAM ? Yparam : d_bufX;
    const float* gbase = d_bufG;

    float acc0, acc1, acc2, acc3;
    const float* self = gbase + (size_t)gw * F + lane * V;
    if constexpr (V == 4) {
        float4 tv = *(const float4*)self;
        acc0 = tv.x; acc1 = tv.y; acc2 = tv.z; acc3 = tv.w;
    } else {
        float2 tv = *(const float2*)self;
        acc0 = tv.x; acc1 = tv.y; acc2 = 0.f; acc3 = 0.f;
    }

    int s = d_off[gw];
    int e = d_off[gw + 1];
    int j = s;
    for (; j + 1 < e; j += 2) {
        int r0 = d_csr[j];
        int r1 = d_csr[j + 1];
        if constexpr (V == 4) {
            float4 v0 = *(const float4*)(gbase + (size_t)r0 * F + lane * 4);
            float4 v1 = *(const float4*)(gbase + (size_t)r1 * F + lane * 4);
            acc0 += v0.x; acc1 += v0.y; acc2 += v0.z; acc3 += v0.w;
            acc0 += v1.x; acc1 += v1.y; acc2 += v1.z; acc3 += v1.w;
        } else {
            float2 v0 = *(const float2*)(gbase + (size_t)r0 * F + lane * 2);
            float2 v1 = *(const float2*)(gbase + (size_t)r1 * F + lane * 2);
            acc0 += v0.x; acc1 += v0.y;
            acc0 += v1.x; acc1 += v1.y;
        }
    }
    if (j < e) {
        int r0 = d_csr[j];
        if constexpr (V == 4) {
            float4 v0 = *(const float4*)(gbase + (size_t)r0 * F + lane * 4);
            acc0 += v0.x; acc1 += v0.y; acc2 += v0.z; acc3 += v0.w;
        } else {
            float2 v0 = *(const float2*)(gbase + (size_t)r0 * F + lane * 2);
            acc0 += v0.x; acc1 += v0.y;
        }
    }

    float dv = d_dinv[gw];
    float* dst = Y + (size_t)gw * F + lane * V;
    if constexpr (V == 4) {
        float4 bv = *(const float4*)(bias + lane * 4);
        float4 o;
        o.x = dv * acc0 + bv.x;
        o.y = dv * acc1 + bv.y;
        o.z = dv * acc2 + bv.z;
        o.w = dv * acc3 + bv.w;
        if (RELU) {
            o.x = fmaxf(o.x, 0.f); o.y = fmaxf(o.y, 0.f);
            o.z = fmaxf(o.z, 0.f); o.w = fmaxf(o.w, 0.f);
        }
        *(float4*)dst = o;
    } else {
        float2 bv = *(const float2*)(bias + lane * 2);
        float2 o;
        o.x = dv * acc0 + bv.x;
        o.y = dv * acc1 + bv.y;
        if (RELU) { o.x = fmaxf(o.x, 0.f); o.y = fmaxf(o.y, 0.f); }
        *(float2*)dst = o;
    }
}

// ---------------- launch ----------------
extern "C" void kernel_launch(void* const* d_in, const int* in_sizes, int n_in,
                              void* d_out, int out_size) {
    const float* x  = (const float*)d_in[0];
    const int*   ei = (const int*)d_in[1];   // int32 or int64 words; auto-detected
    const float* W1 = (const float*)d_in[2];
    const float* b1 = (const float*)d_in[3];
    const float* W2 = (const float*)d_in[4];
    const float* b2 = (const float*)d_in[5];
    const float* W3 = (const float*)d_in[6];
    const float* b3 = (const float*)d_in[7];
    const float* W4 = (const float*)d_in[8];
    const float* b4 = (const float*)d_in[9];
    float* out = (float*)d_out;

    int n = in_sizes[0] / FIN;
    int E = in_sizes[1] / 2;

    // graph build
    detect_kernel<<<1, 32>>>(ei, E);
    deg_init_kernel<<<(n + 255) / 256, 256>>>(n);
    hist_kernel<<<(E + 255) / 256, 256>>>(ei, E);
    int nb = (n + 511) / 512;
    scan1_kernel<<<nb, 512>>>(n);
    scan2_kernel<<<1, 512>>>(nb, n);
    scan3_kernel<<<(n + 255) / 256, 256>>>(n);
    fill_kernel<<<(E + 255) / 256, 256>>>(ei, E);

    int gemm_blocks = (n + 127) / 128;
    int agg_blocks = (n * 32 + 255) / 256;

    // layer 1: x -> bufX (internal)
    gemm_scale_kernel<8, false><<<gemm_blocks, 256>>>(x, W1, n);
    agg_kernel<128, true, false><<<agg_blocks, 256>>>(b1, nullptr, n);
    // layer 2
    gemm_scale_kernel<8, true><<<gemm_blocks, 256>>>(nullptr, W2, n);
    agg_kernel<128, true, false><<<agg_blocks, 256>>>(b2, nullptr, n);
    // layer 3
    gemm_scale_kernel<8, true><<<gemm_blocks, 256>>>(nullptr, W3, n);
    agg_kernel<128, true, false><<<agg_blocks, 256>>>(b3, nullptr, n);
    // layer 4 (OUT=64) -> d_out
    gemm_scale_kernel<4, true><<<gemm_blocks, 256>>>(nullptr, W4, n);
    agg_kernel<64, false, true><<<agg_blocks, 256>>>(b4, out, n);
}